// round 2
// baseline (speedup 1.0000x reference)
#include <cuda_runtime.h>

typedef unsigned long long ull;

#define N_ATOMS   262144
#define TILE      32
#define NTILES    (N_ATOMS / TILE)   /* 8192 */
#define THREADS   512
#define GRID      148

/* ---------------- smem layout (float offsets) ---------------- */
#define OFF_WV1   0                  /* 128x128 = 16384 */
#define OFF_W1A   16384              /* 192x64  = 12288 */
#define OFF_W1B   28672              /* 64x128  = 8192  */
#define OFF_U     36864              /* overlay: L1S[96][128]=12288  */
                                     /* after P1: CTX[32][192]@0, H[32][64]@6144, ST[32][68]@8192 */
#define U_CTX     0
#define U_H       6144
#define U_ST      8192
#define OFF_VW    49152              /* 96 x 65 = 6240 */
#define OFF_GATE  55392              /* 32 x 64 = 2048 */
#define OFF_S     57440              /* small region, 640 */
#define S_B1A 0
#define S_B1B 64
#define S_WV2 192
#define S_W2A 320
#define S_SC  388     /* [0]=b2a, [1]=W2b[0][1], [2]=b2b[1] */
#define S_M0  392
#define S_M1  488
#define S_G2  584
#define SMEM_FLOATS 58080
#define SMEM_BYTES  (SMEM_FLOATS * 4)   /* 232320 B <= 232448 B limit */

__device__ __forceinline__ ull pack2(float x, float y) {
    ull r; asm("mov.b64 %0, {%1, %2};" : "=l"(r) : "f"(x), "f"(y)); return r;
}
__device__ __forceinline__ void unpack2(ull v, float& x, float& y) {
    asm("mov.b64 {%0, %1}, %2;" : "=f"(x), "=f"(y) : "l"(v));
}
__device__ __forceinline__ ull fma2(ull a, ull b, ull c) {
    ull d; asm("fma.rn.f32x2 %0, %1, %2, %3;" : "=l"(d) : "l"(a), "l"(b), "l"(c)); return d;
}
__device__ __forceinline__ float silu(float x) {
    return x * (1.0f / (1.0f + __expf(-x)));
}

__global__ void __launch_bounds__(THREADS, 1)
hessdiag_fused(const float* __restrict__ l0, const float* __restrict__ l1,
               const float* __restrict__ Wv1, const float* __restrict__ W1a,
               const float* __restrict__ b1a, const float* __restrict__ W1b,
               const float* __restrict__ b1b, const float* __restrict__ Wv2,
               const float* __restrict__ W2a, const float* __restrict__ b2a,
               const float* __restrict__ W2b, const float* __restrict__ b2b,
               float* __restrict__ out)
{
    extern __shared__ float sm[];
    const int t = threadIdx.x;

    /* ---- weights -> smem ---- */
    for (int i = t; i < 16384; i += THREADS) sm[OFF_WV1 + i] = Wv1[i];
    for (int i = t; i < 12288; i += THREADS) sm[OFF_W1A + i] = W1a[i];
    for (int i = t; i < 8192;  i += THREADS) sm[OFF_W1B + i] = W1b[i];
    if (t < 64)  sm[OFF_S + S_B1A + t] = b1a[t];
    if (t < 128) sm[OFF_S + S_B1B + t] = b1b[t];
    if (t < 128) sm[OFF_S + S_WV2 + t] = Wv2[t];
    if (t < 65)  sm[OFF_S + S_W2A + t] = W2a[t];
    if (t == 0) {
        sm[OFF_S + S_SC + 0] = b2a[0];
        sm[OFF_S + S_SC + 1] = W2b[1];
        sm[OFF_S + S_SC + 2] = b2b[1];
    }

    const int tx = t & 31;          /* P1 col group: cols 4tx..4tx+3 */
    const int ty = t >> 5;          /* P1 row group: rows 6ty..6ty+5 */
    const int r0 = 6 * ty;
    const int c0 = 4 * tx;
    const int atomP = t >> 4;       /* P2/P3 atom 0..31 */
    const int fg = t & 15;          /* P2/P3 col group */

    /* ---- prefetch first tile into registers ---- */
    float4 pf1[6];   /* l1: 96*128 floats / 512 thr = 24 floats */
    float4 pf0[2];   /* l0: 32*128 floats / 512 thr = 8 floats  */
    {
        int tile0 = blockIdx.x;
        const float4* g1 = reinterpret_cast<const float4*>(l1 + (size_t)tile0 * TILE * 384);
        const float4* g0 = reinterpret_cast<const float4*>(l0 + (size_t)tile0 * TILE * 128);
        #pragma unroll
        for (int i = 0; i < 6; i++) pf1[i] = __ldg(g1 + i * THREADS + t);
        #pragma unroll
        for (int i = 0; i < 2; i++) pf0[i] = __ldg(g0 + i * THREADS + t);
    }

    for (int tile = blockIdx.x; tile < NTILES; tile += GRID) {
        /* ---- store prefetched l1 -> L1S (direct row-major [96][128]) ---- */
        {
            float4* Ld = reinterpret_cast<float4*>(sm + OFF_U);
            #pragma unroll
            for (int i = 0; i < 6; i++) Ld[i * THREADS + t] = pf1[i];
        }
        __syncthreads();   /* S1: L1S ready (also orders weight stores on iter 0) */

        /* ---- P1: vmix = L1S(96x128) @ Wv1(128x128), f32x2 ---- */
        ull acc[6][2];
        {
            const ull z = pack2(0.f, 0.f);
            #pragma unroll
            for (int j = 0; j < 6; j++) { acc[j][0] = z; acc[j][1] = z; }
            const float* Lp = sm + OFF_U + r0 * 128;
            const float* Wp = sm + OFF_WV1 + c0;
            #pragma unroll 2
            for (int k = 0; k < 128; k += 4) {
                float4 wv[4];
                #pragma unroll
                for (int kk = 0; kk < 4; kk++)
                    wv[kk] = *reinterpret_cast<const float4*>(Wp + (k + kk) * 128);
                float4 Lr[6];
                #pragma unroll
                for (int j = 0; j < 6; j++)
                    Lr[j] = *reinterpret_cast<const float4*>(Lp + j * 128 + k);
                #pragma unroll
                for (int kk = 0; kk < 4; kk++) {
                    ull b0 = pack2(wv[kk].x, wv[kk].y);
                    ull b1 = pack2(wv[kk].z, wv[kk].w);
                    #pragma unroll
                    for (int j = 0; j < 6; j++) {
                        float a = (&Lr[j].x)[kk];
                        ull a2 = pack2(a, a);
                        acc[j][0] = fma2(a2, b0, acc[j][0]);
                        acc[j][1] = fma2(a2, b1, acc[j][1]);
                    }
                }
            }
        }
        /* unpack */
        float v[6][4];
        #pragma unroll
        for (int j = 0; j < 6; j++) {
            unpack2(acc[j][0], v[j][0], v[j][1]);
            unpack2(acc[j][1], v[j][2], v[j][3]);
        }
        /* tx>=16: these cols are vW -> store to VW (outside overlay, safe pre-sync) */
        if (tx >= 16) {
            #pragma unroll
            for (int j = 0; j < 6; j++) {
                float* p = &sm[OFF_VW + (r0 + j) * 65 + (c0 - 64)];
                p[0] = v[j][0]; p[1] = v[j][1]; p[2] = v[j][2]; p[3] = v[j][3];
            }
        }
        /* tx<16: vV -> norms (kept in regs until after sync) */
        float vn[2][4];
        if (tx < 16) {
            #pragma unroll
            for (int i = 0; i < 2; i++) {
                #pragma unroll
                for (int c = 0; c < 4; c++) {
                    float s2 = v[3 * i + 0][c] * v[3 * i + 0][c]
                             + v[3 * i + 1][c] * v[3 * i + 1][c]
                             + v[3 * i + 2][c] * v[3 * i + 2][c];
                    vn[i][c] = sqrtf(s2);
                }
            }
        }
        __syncthreads();   /* S2: all L1S reads done -> overlay reusable */

        /* ---- build CTX[32][192]: rows = atoms; feats 0..127 = l0, 128..191 = |vV| ---- */
        {
            #pragma unroll
            for (int i = 0; i < 2; i++) {
                int o = (i * THREADS + t) * 4;
                int atom = o >> 7, k = o & 127;
                *reinterpret_cast<float4*>(sm + OFF_U + U_CTX + atom * 192 + k) = pf0[i];
            }
            if (tx < 16) {
                #pragma unroll
                for (int i = 0; i < 2; i++)
                    #pragma unroll
                    for (int c = 0; c < 4; c++)
                        sm[OFF_U + U_CTX + (2 * ty + i) * 192 + 128 + c0 + c] = vn[i][c];
            }
        }
        /* ---- issue prefetch for next tile (regs consumed above) ---- */
        {
            int nt = tile + GRID;
            int pt = (nt < NTILES) ? nt : blockIdx.x;
            const float4* g1 = reinterpret_cast<const float4*>(l1 + (size_t)pt * TILE * 384);
            const float4* g0 = reinterpret_cast<const float4*>(l0 + (size_t)pt * TILE * 128);
            #pragma unroll
            for (int i = 0; i < 6; i++) pf1[i] = __ldg(g1 + i * THREADS + t);
            #pragma unroll
            for (int i = 0; i < 2; i++) pf0[i] = __ldg(g0 + i * THREADS + t);
        }
        __syncthreads();   /* S3: CTX ready */

        /* ---- P2: h = silu(ctx @ W1a + b1a): 32 x 64, f32x2 ---- */
        {
            ull h01 = pack2(sm[OFF_S + S_B1A + 4 * fg + 0], sm[OFF_S + S_B1A + 4 * fg + 1]);
            ull h23 = pack2(sm[OFF_S + S_B1A + 4 * fg + 2], sm[OFF_S + S_B1A + 4 * fg + 3]);
            const float* Cp = sm + OFF_U + U_CTX + atomP * 192;
            const float* Wp = sm + OFF_W1A + 4 * fg;
            #pragma unroll 2
            for (int k = 0; k < 192; k += 4) {
                float4 a4 = *reinterpret_cast<const float4*>(Cp + k);
                #pragma unroll
                for (int kk = 0; kk < 4; kk++) {
                    float a = (&a4.x)[kk];
                    ull a2 = pack2(a, a);
                    float4 w = *reinterpret_cast<const float4*>(Wp + (k + kk) * 64);
                    h01 = fma2(a2, pack2(w.x, w.y), h01);
                    h23 = fma2(a2, pack2(w.z, w.w), h23);
                }
            }
            float h0, h1, h2, h3;
            unpack2(h01, h0, h1); unpack2(h23, h2, h3);
            float4 hv = make_float4(silu(h0), silu(h1), silu(h2), silu(h3));
            *reinterpret_cast<float4*>(sm + OFF_U + U_H + atomP * 64 + 4 * fg) = hv;
        }
        __syncthreads();   /* S4: H ready */

        /* ---- P3: y = h @ W1b + b1b: 32 x 128, f32x2 ---- */
        {
            const int cb = 8 * fg;
            ull y01 = pack2(sm[OFF_S + S_B1B + cb + 0], sm[OFF_S + S_B1B + cb + 1]);
            ull y23 = pack2(sm[OFF_S + S_B1B + cb + 2], sm[OFF_S + S_B1B + cb + 3]);
            ull y45 = pack2(sm[OFF_S + S_B1B + cb + 4], sm[OFF_S + S_B1B + cb + 5]);
            ull y67 = pack2(sm[OFF_S + S_B1B + cb + 6], sm[OFF_S + S_B1B + cb + 7]);
            const float* Hp = sm + OFF_U + U_H + atomP * 64;
            const float* Wp = sm + OFF_W1B + cb;
            #pragma unroll 2
            for (int k = 0; k < 64; k += 4) {
                float4 a4 = *reinterpret_cast<const float4*>(Hp + k);
                #pragma unroll
                for (int kk = 0; kk < 4; kk++) {
                    float a = (&a4.x)[kk];
                    ull a2 = pack2(a, a);
                    float4 wA = *reinterpret_cast<const float4*>(Wp + (k + kk) * 128);
                    float4 wB = *reinterpret_cast<const float4*>(Wp + (k + kk) * 128 + 4);
                    y01 = fma2(a2, pack2(wA.x, wA.y), y01);
                    y23 = fma2(a2, pack2(wA.z, wA.w), y23);
                    y45 = fma2(a2, pack2(wB.x, wB.y), y45);
                    y67 = fma2(a2, pack2(wB.z, wB.w), y67);
                }
            }
            float f0, f1, f2, f3, f4, f5, f6, f7;
            unpack2(y01, f0, f1); unpack2(y23, f2, f3);
            unpack2(y45, f4, f5); unpack2(y67, f6, f7);
            if (fg < 8) {  /* cols cb..cb+7 all < 64 -> s_out (silu) */
                float4 s0 = make_float4(silu(f0), silu(f1), silu(f2), silu(f3));
                float4 s1 = make_float4(silu(f4), silu(f5), silu(f6), silu(f7));
                *reinterpret_cast<float4*>(sm + OFF_U + U_ST + atomP * 68 + cb)     = s0;
                *reinterpret_cast<float4*>(sm + OFF_U + U_ST + atomP * 68 + cb + 4) = s1;
            } else {       /* cols >= 64 -> gate */
                float4 g0v = make_float4(f0, f1, f2, f3);
                float4 g1v = make_float4(f4, f5, f6, f7);
                *reinterpret_cast<float4*>(sm + OFF_GATE + atomP * 64 + cb - 64)     = g0v;
                *reinterpret_cast<float4*>(sm + OFF_GATE + atomP * 64 + cb - 64 + 4) = g1v;
            }
        }
        __syncthreads();   /* S5: ST, GATE ready (VW synced earlier) */

        /* ---- P4: vmix2[r][0..1] = sum_f gate[n][f]*vW[r][f]*Wv2[f][:] ---- */
        if (t < 96) {
            int n = t / 3;
            const float* G  = &sm[OFF_GATE + n * 64];
            const float* V  = &sm[OFF_VW + t * 65];
            const float* S2 = &sm[OFF_S + S_WV2];
            float m0 = 0.f, m1 = 0.f;
            #pragma unroll 8
            for (int f = 0; f < 64; f++) {
                float p = G[f] * V[f];
                m0 += p * S2[2 * f];
                m1 += p * S2[2 * f + 1];
            }
            sm[OFF_S + S_M0 + t] = m0;
            sm[OFF_S + S_M1 + t] = m1;
        }
        __syncthreads();   /* S6 */

        /* ---- P5: scalar head per atom ---- */
        if (t < 32) {
            float q0 = sm[OFF_S + S_M0 + 3 * t + 0];
            float q1 = sm[OFF_S + S_M0 + 3 * t + 1];
            float q2 = sm[OFF_S + S_M0 + 3 * t + 2];
            float d = sm[OFF_S + S_SC + 0] +
                      sqrtf(q0 * q0 + q1 * q1 + q2 * q2) * sm[OFF_S + S_W2A + 64];
            const float* S = sm + OFF_U + U_ST + t * 68;
            #pragma unroll
            for (int k = 0; k < 64; k += 4) {
                float4 sv = *reinterpret_cast<const float4*>(S + k);
                d += sv.x * sm[OFF_S + S_W2A + k + 0]
                   + sv.y * sm[OFF_S + S_W2A + k + 1]
                   + sv.z * sm[OFF_S + S_W2A + k + 2]
                   + sv.w * sm[OFF_S + S_W2A + k + 3];
            }
            float h2 = silu(d);
            sm[OFF_S + S_G2 + t] = 1000.f * (h2 * sm[OFF_S + S_SC + 1] + sm[OFF_S + S_SC + 2]);
        }
        __syncthreads();   /* S7: also protects overlay before next L1S store */

        /* ---- P6: out = gate2 * vmix2_col1 (coalesced) ---- */
        if (t < 96) {
            out[(size_t)tile * 96 + t] = sm[OFF_S + S_G2 + t / 3] * sm[OFF_S + S_M1 + t];
        }
        /* next-iter L1S store only conflicts with overlay reads, all done pre-S7 */
    }
}

extern "C" void kernel_launch(void* const* d_in, const int* in_sizes, int n_in,
                              void* d_out, int out_size) {
    const float* l0  = (const float*)d_in[0];
    const float* l1  = (const float*)d_in[1];
    /* d_in[2] = idx_m (unused) */
    const float* Wv1 = (const float*)d_in[3];
    const float* W1a = (const float*)d_in[4];
    const float* b1a = (const float*)d_in[5];
    const float* W1b = (const float*)d_in[6];
    const float* b1b = (const float*)d_in[7];
    const float* Wv2 = (const float*)d_in[8];
    const float* W2a = (const float*)d_in[9];
    const float* b2a = (const float*)d_in[10];
    const float* W2b = (const float*)d_in[11];
    const float* b2b = (const float*)d_in[12];

    cudaFuncSetAttribute(hessdiag_fused,
                         cudaFuncAttributeMaxDynamicSharedMemorySize, SMEM_BYTES);
    hessdiag_fused<<<GRID, THREADS, SMEM_BYTES>>>(
        l0, l1, Wv1, W1a, b1a, W1b, b1b, Wv2, W2a, b2a, W2b, b2b, (float*)d_out);
}

// round 3
// speedup vs baseline: 1.0010x; 1.0010x over previous
#include <cuda_runtime.h>

typedef unsigned long long ull;

#define N_ATOMS   262144
#define TILE      32
#define NTILES    (N_ATOMS / TILE)   /* 8192 */
#define THREADS   512
#define GRID      148

/* ---------------- smem layout (float offsets) ---------------- */
#define OFF_WV1   0                  /* 128x128 = 16384 */
#define OFF_W1A   16384              /* 192x64  = 12288 */
#define OFF_W1B   28672              /* 64x128  = 8192  */
#define OFF_U     36864              /* overlay: L1S[96][128]=12288  */
                                     /* after P1: CTX[32][192]@0, H[32][64]@6144, ST[32][68]@8192 */
#define U_CTX     0
#define U_H       6144
#define U_ST      8192
#define OFF_VW    49152              /* 96 x 65 = 6240 */
#define OFF_GATE  55392              /* 32 x 64 = 2048 */
#define OFF_S     57440              /* small region, 640 */
#define S_B1A 0
#define S_B1B 64
#define S_WV2 192
#define S_W2A 320
#define S_SC  388     /* [0]=b2a, [1]=W2b[0][1], [2]=b2b[1] */
#define S_M0  392
#define S_M1  488
#define S_G2  584
#define SMEM_FLOATS 58080
#define SMEM_BYTES  (SMEM_FLOATS * 4)   /* 232320 B <= 232448 B limit */

__device__ __forceinline__ ull pack2(float x, float y) {
    ull r; asm("mov.b64 %0, {%1, %2};" : "=l"(r) : "f"(x), "f"(y)); return r;
}
__device__ __forceinline__ void unpack2(ull v, float& x, float& y) {
    asm("mov.b64 {%0, %1}, %2;" : "=f"(x), "=f"(y) : "l"(v));
}
__device__ __forceinline__ ull fma2(ull a, ull b, ull c) {
    ull d; asm("fma.rn.f32x2 %0, %1, %2, %3;" : "=l"(d) : "l"(a), "l"(b), "l"(c)); return d;
}
__device__ __forceinline__ float silu(float x) {
    return x * (1.0f / (1.0f + __expf(-x)));
}

__global__ void __launch_bounds__(THREADS, 1)
hessdiag_fused(const float* __restrict__ l0, const float* __restrict__ l1,
               const float* __restrict__ Wv1, const float* __restrict__ W1a,
               const float* __restrict__ b1a, const float* __restrict__ W1b,
               const float* __restrict__ b1b, const float* __restrict__ Wv2,
               const float* __restrict__ W2a, const float* __restrict__ b2a,
               const float* __restrict__ W2b, const float* __restrict__ b2b,
               float* __restrict__ out)
{
    extern __shared__ float sm[];
    const int t = threadIdx.x;

    /* ---- weights -> smem ---- */
    for (int i = t; i < 16384; i += THREADS) sm[OFF_WV1 + i] = Wv1[i];
    for (int i = t; i < 12288; i += THREADS) sm[OFF_W1A + i] = W1a[i];
    for (int i = t; i < 8192;  i += THREADS) sm[OFF_W1B + i] = W1b[i];
    if (t < 64)  sm[OFF_S + S_B1A + t] = b1a[t];
    if (t < 128) sm[OFF_S + S_B1B + t] = b1b[t];
    if (t < 128) sm[OFF_S + S_WV2 + t] = Wv2[t];
    if (t < 65)  sm[OFF_S + S_W2A + t] = W2a[t];
    if (t == 0) {
        sm[OFF_S + S_SC + 0] = b2a[0];
        sm[OFF_S + S_SC + 1] = W2b[1];
        sm[OFF_S + S_SC + 2] = b2b[1];
    }

    const int tx = t & 31;          /* P1 col group: cols 4tx..4tx+3 */
    const int ty = t >> 5;          /* P1 row group: rows 6ty..6ty+5 */
    const int r0 = 6 * ty;
    const int c0 = 4 * tx;
    const int atomP = t >> 4;       /* P2/P3 atom 0..31 */
    const int fg = t & 15;          /* P2/P3 col group */

    /* ---- prefetch first tile into registers ---- */
    float4 pf1[6];   /* l1: 96*128 floats / 512 thr = 24 floats */
    float4 pf0[2];   /* l0: 32*128 floats / 512 thr = 8 floats  */
    {
        int tile0 = blockIdx.x;
        const float4* g1 = reinterpret_cast<const float4*>(l1 + (size_t)tile0 * TILE * 384);
        const float4* g0 = reinterpret_cast<const float4*>(l0 + (size_t)tile0 * TILE * 128);
        #pragma unroll
        for (int i = 0; i < 6; i++) pf1[i] = __ldg(g1 + i * THREADS + t);
        #pragma unroll
        for (int i = 0; i < 2; i++) pf0[i] = __ldg(g0 + i * THREADS + t);
    }

    for (int tile = blockIdx.x; tile < NTILES; tile += GRID) {
        /* ---- store prefetched l1 -> L1S (direct row-major [96][128]) ---- */
        {
            float4* Ld = reinterpret_cast<float4*>(sm + OFF_U);
            #pragma unroll
            for (int i = 0; i < 6; i++) Ld[i * THREADS + t] = pf1[i];
        }
        __syncthreads();   /* S1: L1S ready (also orders weight stores on iter 0) */

        /* ---- P1: vmix = L1S(96x128) @ Wv1(128x128), f32x2 ---- */
        ull acc[6][2];
        {
            const ull z = pack2(0.f, 0.f);
            #pragma unroll
            for (int j = 0; j < 6; j++) { acc[j][0] = z; acc[j][1] = z; }
            const float* Lp = sm + OFF_U + r0 * 128;
            const float* Wp = sm + OFF_WV1 + c0;
            #pragma unroll 2
            for (int k = 0; k < 128; k += 4) {
                float4 wv[4];
                #pragma unroll
                for (int kk = 0; kk < 4; kk++)
                    wv[kk] = *reinterpret_cast<const float4*>(Wp + (k + kk) * 128);
                float4 Lr[6];
                #pragma unroll
                for (int j = 0; j < 6; j++)
                    Lr[j] = *reinterpret_cast<const float4*>(Lp + j * 128 + k);
                #pragma unroll
                for (int kk = 0; kk < 4; kk++) {
                    ull b0 = pack2(wv[kk].x, wv[kk].y);
                    ull b1 = pack2(wv[kk].z, wv[kk].w);
                    #pragma unroll
                    for (int j = 0; j < 6; j++) {
                        float a = (&Lr[j].x)[kk];
                        ull a2 = pack2(a, a);
                        acc[j][0] = fma2(a2, b0, acc[j][0]);
                        acc[j][1] = fma2(a2, b1, acc[j][1]);
                    }
                }
            }
        }
        /* unpack */
        float v[6][4];
        #pragma unroll
        for (int j = 0; j < 6; j++) {
            unpack2(acc[j][0], v[j][0], v[j][1]);
            unpack2(acc[j][1], v[j][2], v[j][3]);
        }
        /* tx>=16: these cols are vW -> store to VW (outside overlay, safe pre-sync) */
        if (tx >= 16) {
            #pragma unroll
            for (int j = 0; j < 6; j++) {
                float* p = &sm[OFF_VW + (r0 + j) * 65 + (c0 - 64)];
                p[0] = v[j][0]; p[1] = v[j][1]; p[2] = v[j][2]; p[3] = v[j][3];
            }
        }
        /* tx<16: vV -> norms (kept in regs until after sync) */
        float vn[2][4];
        if (tx < 16) {
            #pragma unroll
            for (int i = 0; i < 2; i++) {
                #pragma unroll
                for (int c = 0; c < 4; c++) {
                    float s2 = v[3 * i + 0][c] * v[3 * i + 0][c]
                             + v[3 * i + 1][c] * v[3 * i + 1][c]
                             + v[3 * i + 2][c] * v[3 * i + 2][c];
                    vn[i][c] = sqrtf(s2);
                }
            }
        }
        __syncthreads();   /* S2: all L1S reads done -> overlay reusable */

        /* ---- build CTX[32][192]: rows = atoms; feats 0..127 = l0, 128..191 = |vV| ---- */
        {
            #pragma unroll
            for (int i = 0; i < 2; i++) {
                int o = (i * THREADS + t) * 4;
                int atom = o >> 7, k = o & 127;
                *reinterpret_cast<float4*>(sm + OFF_U + U_CTX + atom * 192 + k) = pf0[i];
            }
            if (tx < 16) {
                #pragma unroll
                for (int i = 0; i < 2; i++)
                    #pragma unroll
                    for (int c = 0; c < 4; c++)
                        sm[OFF_U + U_CTX + (2 * ty + i) * 192 + 128 + c0 + c] = vn[i][c];
            }
        }
        /* ---- issue prefetch for next tile (regs consumed above) ---- */
        {
            int nt = tile + GRID;
            int pt = (nt < NTILES) ? nt : blockIdx.x;
            const float4* g1 = reinterpret_cast<const float4*>(l1 + (size_t)pt * TILE * 384);
            const float4* g0 = reinterpret_cast<const float4*>(l0 + (size_t)pt * TILE * 128);
            #pragma unroll
            for (int i = 0; i < 6; i++) pf1[i] = __ldg(g1 + i * THREADS + t);
            #pragma unroll
            for (int i = 0; i < 2; i++) pf0[i] = __ldg(g0 + i * THREADS + t);
        }
        __syncthreads();   /* S3: CTX ready */

        /* ---- P2: h = silu(ctx @ W1a + b1a): 32 x 64, f32x2 ---- */
        {
            ull h01 = pack2(sm[OFF_S + S_B1A + 4 * fg + 0], sm[OFF_S + S_B1A + 4 * fg + 1]);
            ull h23 = pack2(sm[OFF_S + S_B1A + 4 * fg + 2], sm[OFF_S + S_B1A + 4 * fg + 3]);
            const float* Cp = sm + OFF_U + U_CTX + atomP * 192;
            const float* Wp = sm + OFF_W1A + 4 * fg;
            #pragma unroll 2
            for (int k = 0; k < 192; k += 4) {
                float4 a4 = *reinterpret_cast<const float4*>(Cp + k);
                #pragma unroll
                for (int kk = 0; kk < 4; kk++) {
                    float a = (&a4.x)[kk];
                    ull a2 = pack2(a, a);
                    float4 w = *reinterpret_cast<const float4*>(Wp + (k + kk) * 64);
                    h01 = fma2(a2, pack2(w.x, w.y), h01);
                    h23 = fma2(a2, pack2(w.z, w.w), h23);
                }
            }
            float h0, h1, h2, h3;
            unpack2(h01, h0, h1); unpack2(h23, h2, h3);
            float4 hv = make_float4(silu(h0), silu(h1), silu(h2), silu(h3));
            *reinterpret_cast<float4*>(sm + OFF_U + U_H + atomP * 64 + 4 * fg) = hv;
        }
        __syncthreads();   /* S4: H ready */

        /* ---- P3: y = h @ W1b + b1b: 32 x 128, f32x2 ---- */
        {
            const int cb = 8 * fg;
            ull y01 = pack2(sm[OFF_S + S_B1B + cb + 0], sm[OFF_S + S_B1B + cb + 1]);
            ull y23 = pack2(sm[OFF_S + S_B1B + cb + 2], sm[OFF_S + S_B1B + cb + 3]);
            ull y45 = pack2(sm[OFF_S + S_B1B + cb + 4], sm[OFF_S + S_B1B + cb + 5]);
            ull y67 = pack2(sm[OFF_S + S_B1B + cb + 6], sm[OFF_S + S_B1B + cb + 7]);
            const float* Hp = sm + OFF_U + U_H + atomP * 64;
            const float* Wp = sm + OFF_W1B + cb;
            #pragma unroll 2
            for (int k = 0; k < 64; k += 4) {
                float4 a4 = *reinterpret_cast<const float4*>(Hp + k);
                #pragma unroll
                for (int kk = 0; kk < 4; kk++) {
                    float a = (&a4.x)[kk];
                    ull a2 = pack2(a, a);
                    float4 wA = *reinterpret_cast<const float4*>(Wp + (k + kk) * 128);
                    float4 wB = *reinterpret_cast<const float4*>(Wp + (k + kk) * 128 + 4);
                    y01 = fma2(a2, pack2(wA.x, wA.y), y01);
                    y23 = fma2(a2, pack2(wA.z, wA.w), y23);
                    y45 = fma2(a2, pack2(wB.x, wB.y), y45);
                    y67 = fma2(a2, pack2(wB.z, wB.w), y67);
                }
            }
            float f0, f1, f2, f3, f4, f5, f6, f7;
            unpack2(y01, f0, f1); unpack2(y23, f2, f3);
            unpack2(y45, f4, f5); unpack2(y67, f6, f7);
            if (fg < 8) {  /* cols cb..cb+7 all < 64 -> s_out (silu) */
                float4 s0 = make_float4(silu(f0), silu(f1), silu(f2), silu(f3));
                float4 s1 = make_float4(silu(f4), silu(f5), silu(f6), silu(f7));
                *reinterpret_cast<float4*>(sm + OFF_U + U_ST + atomP * 68 + cb)     = s0;
                *reinterpret_cast<float4*>(sm + OFF_U + U_ST + atomP * 68 + cb + 4) = s1;
            } else {       /* cols >= 64 -> gate */
                float4 g0v = make_float4(f0, f1, f2, f3);
                float4 g1v = make_float4(f4, f5, f6, f7);
                *reinterpret_cast<float4*>(sm + OFF_GATE + atomP * 64 + cb - 64)     = g0v;
                *reinterpret_cast<float4*>(sm + OFF_GATE + atomP * 64 + cb - 64 + 4) = g1v;
            }
        }
        __syncthreads();   /* S5: ST, GATE ready (VW synced earlier) */

        /* ---- P4: vmix2[r][0..1] = sum_f gate[n][f]*vW[r][f]*Wv2[f][:] ---- */
        if (t < 96) {
            int n = t / 3;
            const float* G  = &sm[OFF_GATE + n * 64];
            const float* V  = &sm[OFF_VW + t * 65];
            const float* S2 = &sm[OFF_S + S_WV2];
            float m0 = 0.f, m1 = 0.f;
            #pragma unroll 8
            for (int f = 0; f < 64; f++) {
                float p = G[f] * V[f];
                m0 += p * S2[2 * f];
                m1 += p * S2[2 * f + 1];
            }
            sm[OFF_S + S_M0 + t] = m0;
            sm[OFF_S + S_M1 + t] = m1;
        }
        __syncthreads();   /* S6 */

        /* ---- P5: scalar head per atom ---- */
        if (t < 32) {
            float q0 = sm[OFF_S + S_M0 + 3 * t + 0];
            float q1 = sm[OFF_S + S_M0 + 3 * t + 1];
            float q2 = sm[OFF_S + S_M0 + 3 * t + 2];
            float d = sm[OFF_S + S_SC + 0] +
                      sqrtf(q0 * q0 + q1 * q1 + q2 * q2) * sm[OFF_S + S_W2A + 64];
            const float* S = sm + OFF_U + U_ST + t * 68;
            #pragma unroll
            for (int k = 0; k < 64; k += 4) {
                float4 sv = *reinterpret_cast<const float4*>(S + k);
                d += sv.x * sm[OFF_S + S_W2A + k + 0]
                   + sv.y * sm[OFF_S + S_W2A + k + 1]
                   + sv.z * sm[OFF_S + S_W2A + k + 2]
                   + sv.w * sm[OFF_S + S_W2A + k + 3];
            }
            float h2 = silu(d);
            sm[OFF_S + S_G2 + t] = 1000.f * (h2 * sm[OFF_S + S_SC + 1] + sm[OFF_S + S_SC + 2]);
        }
        __syncthreads();   /* S7: also protects overlay before next L1S store */

        /* ---- P6: out = gate2 * vmix2_col1 (coalesced) ---- */
        if (t < 96) {
            out[(size_t)tile * 96 + t] = sm[OFF_S + S_G2 + t / 3] * sm[OFF_S + S_M1 + t];
        }
        /* next-iter L1S store only conflicts with overlay reads, all done pre-S7 */
    }
}

extern "C" void kernel_launch(void* const* d_in, const int* in_sizes, int n_in,
                              void* d_out, int out_size) {
    const float* l0  = (const float*)d_in[0];
    const float* l1  = (const float*)d_in[1];
    /* d_in[2] = idx_m (unused) */
    const float* Wv1 = (const float*)d_in[3];
    const float* W1a = (const float*)d_in[4];
    const float* b1a = (const float*)d_in[5];
    const float* W1b = (const float*)d_in[6];
    const float* b1b = (const float*)d_in[7];
    const float* Wv2 = (const float*)d_in[8];
    const float* W2a = (const float*)d_in[9];
    const float* b2a = (const float*)d_in[10];
    const float* W2b = (const float*)d_in[11];
    const float* b2b = (const float*)d_in[12];

    cudaFuncSetAttribute(hessdiag_fused,
                         cudaFuncAttributeMaxDynamicSharedMemorySize, SMEM_BYTES);
    hessdiag_fused<<<GRID, THREADS, SMEM_BYTES>>>(
        l0, l1, Wv1, W1a, b1a, W1b, b1b, Wv2, W2a, b2a, W2b, b2b, (float*)d_out);
}

// round 5
// speedup vs baseline: 2.3282x; 2.3258x over previous
#include <cuda_runtime.h>
#include <cuda_bf16.h>
#include <cstdint>

typedef uint32_t u32;

#define THREADS 256
#define GRID    148
#define NBLK    2048

/* ---- smem byte offsets ---- */
#define B_WV1H 0        /* Wv1 [128k][128n] bf16 hi, XOR-swizzled, 32768 */
#define B_WV1L 32768
#define B_W1AH 65536    /* W1a [192k][64n] 24576 */
#define B_W1AL 90112
#define B_W1BH 114688   /* W1b [64k][128n] 16384 */
#define B_W1BL 131072
#define B_ACTH 147456   /* act [128m][64k] bf16 16384 */
#define B_ACTL 163840
#define B_GATE 180224   /* f32 [128][68] = 34816 */
#define GATE_P 68
#define B_DARR 215040   /* f32 [128] */
#define B_PM0  215552   /* f32 [128][3] */
#define B_PM1  217088   /* f32 [128][3] */
#define B_SMALL 218624  /* biases etc */
#define SMEM_BYTES 220288

#define SB_B1A 0
#define SB_B1B 64
#define SB_WV2 192
#define SB_W2A 320
#define SB_C   385   /* b2a, W2b[1], b2b[1] */

static __device__ __forceinline__ u32 s2u(const void* p) {
    u32 a; asm("{ .reg .u64 t; cvta.to.shared.u64 t, %1; cvt.u32.u64 %0, t; }" : "=r"(a) : "l"(p)); return a;
}
static __device__ __forceinline__ void ldmx4(u32& r0, u32& r1, u32& r2, u32& r3, u32 a) {
    asm volatile("ldmatrix.sync.aligned.m8n8.x4.shared.b16 {%0,%1,%2,%3}, [%4];"
                 : "=r"(r0), "=r"(r1), "=r"(r2), "=r"(r3) : "r"(a));
}
static __device__ __forceinline__ void ldmx2t(u32& r0, u32& r1, u32 a) {
    asm volatile("ldmatrix.sync.aligned.m8n8.x2.trans.shared.b16 {%0,%1}, [%2];"
                 : "=r"(r0), "=r"(r1) : "r"(a));
}
static __device__ __forceinline__ void mmabf(float* d, const u32* a, const u32* b) {
    asm volatile("mma.sync.aligned.m16n8k16.row.col.f32.bf16.bf16.f32 "
                 "{%0,%1,%2,%3}, {%4,%5,%6,%7}, {%8,%9}, {%0,%1,%2,%3};"
                 : "+f"(d[0]), "+f"(d[1]), "+f"(d[2]), "+f"(d[3])
                 : "r"(a[0]), "r"(a[1]), "r"(a[2]), "r"(a[3]), "r"(b[0]), "r"(b[1]));
}
static __device__ __forceinline__ float silu(float x) {
    return x * (1.0f / (1.0f + __expf(-x)));
}
static __device__ __forceinline__ void split2(float x, float y, u32& hi, u32& lo) {
    __nv_bfloat16 hx = __float2bfloat16(x), hy = __float2bfloat16(y);
    __nv_bfloat16 lx = __float2bfloat16(x - __bfloat162float(hx));
    __nv_bfloat16 ly = __float2bfloat16(y - __bfloat162float(hy));
    hi = (u32)__bfloat16_as_ushort(hx) | ((u32)__bfloat16_as_ushort(hy) << 16);
    lo = (u32)__bfloat16_as_ushort(lx) | ((u32)__bfloat16_as_ushort(ly) << 16);
}
/* weight store: [k][n] bf16 tile, row = rowB bytes, chunk XOR swizzle */
static __device__ __forceinline__ void wst(char* smc, int offH, int offL, int rowB,
                                           int k, int n, float x) {
    __nv_bfloat16 h = __float2bfloat16(x);
    __nv_bfloat16 l = __float2bfloat16(x - __bfloat162float(h));
    int off = k * rowB + ((((n >> 3) ^ (k & 7))) << 4) + ((n & 7) << 1);
    *reinterpret_cast<__nv_bfloat16*>(smc + offH + off) = h;
    *reinterpret_cast<__nv_bfloat16*>(smc + offL + off) = l;
}
/* act tile [128m][64k]: 4 consecutive k (k4 % 4 == 0) */
static __device__ __forceinline__ void act_st4(char* smc, int row, int k4, float4 v) {
    u32 h0, l0, h1, l1;
    split2(v.x, v.y, h0, l0); split2(v.z, v.w, h1, l1);
    int off = row * 128 + ((((k4 >> 3) ^ (row & 7))) << 4) + ((k4 & 7) << 1);
    *reinterpret_cast<uint2*>(smc + B_ACTH + off) = make_uint2(h0, h1);
    *reinterpret_cast<uint2*>(smc + B_ACTL + off) = make_uint2(l0, l1);
}
static __device__ __forceinline__ void act_st1(char* smc, int row, int k, float x) {
    __nv_bfloat16 h = __float2bfloat16(x);
    __nv_bfloat16 l = __float2bfloat16(x - __bfloat162float(h));
    int off = row * 128 + ((((k >> 3) ^ (row & 7))) << 4) + ((k & 7) << 1);
    *reinterpret_cast<__nv_bfloat16*>(smc + B_ACTH + off) = h;
    *reinterpret_cast<__nv_bfloat16*>(smc + B_ACTL + off) = l;
}

/* one GEMM pass over the staged 64-k activation buffer */
template<int MT, int NT, int KS>
static __device__ __forceinline__ void gemm_pass(
    float (&acc)[MT][NT][4], u32 actH, int m0, int rA, int kh,
    u32 bH, int rowB, int n0, int kg0, int lane)
{
    #pragma unroll
    for (int s = 0; s < KS; s++) {
        u32 ah[MT][4], al[MT][4];
        #pragma unroll
        for (int mt = 0; mt < MT; mt++) {
            int row = m0 + mt * 16 + rA;
            u32 a = actH + row * 128 + ((((2 * s + kh) ^ (row & 7))) << 4);
            ldmx4(ah[mt][0], ah[mt][1], ah[mt][2], ah[mt][3], a);
            ldmx4(al[mt][0], al[mt][1], al[mt][2], al[mt][3], a + 16384u);
        }
        int kb = kg0 + s * 16 + (lane & 15);
        #pragma unroll
        for (int nt = 0; nt < NT; nt++) {
            int n = n0 + nt * 8;
            u32 b = bH + kb * rowB + ((((n >> 3) ^ (kb & 7))) << 4);
            u32 bh[2], bl[2];
            ldmx2t(bh[0], bh[1], b);
            ldmx2t(bl[0], bl[1], b + 24576u); /* all weight hi->lo gaps = 24576 or 16384; passed via rowB trick below */
            #pragma unroll
            for (int mt = 0; mt < MT; mt++) {
                mmabf(acc[mt][nt], ah[mt], bh);
                mmabf(acc[mt][nt], ah[mt], bl);
                mmabf(acc[mt][nt], al[mt], bh);
            }
        }
    }
}
/* variant with explicit hi->lo gap (Wv1/W1b gap = 32768/16384, W1a = 24576) */
template<int MT, int NT, int KS>
static __device__ __forceinline__ void gemm_passg(
    float (&acc)[MT][NT][4], u32 actH, int m0, int rA, int kh,
    u32 bH, u32 gap, int rowB, int n0, int kg0, int lane)
{
    #pragma unroll
    for (int s = 0; s < KS; s++) {
        u32 ah[MT][4], al[MT][4];
        #pragma unroll
        for (int mt = 0; mt < MT; mt++) {
            int row = m0 + mt * 16 + rA;
            u32 a = actH + row * 128 + ((((2 * s + kh) ^ (row & 7))) << 4);
            ldmx4(ah[mt][0], ah[mt][1], ah[mt][2], ah[mt][3], a);
            ldmx4(al[mt][0], al[mt][1], al[mt][2], al[mt][3], a + 16384u);
        }
        int kb = kg0 + s * 16 + (lane & 15);
        #pragma unroll
        for (int nt = 0; nt < NT; nt++) {
            int n = n0 + nt * 8;
            u32 b = bH + kb * rowB + ((((n >> 3) ^ (kb & 7))) << 4);
            u32 bh[2], bl[2];
            ldmx2t(bh[0], bh[1], b);
            ldmx2t(bl[0], bl[1], b + gap);
            #pragma unroll
            for (int mt = 0; mt < MT; mt++) {
                mmabf(acc[mt][nt], ah[mt], bh);
                mmabf(acc[mt][nt], ah[mt], bl);
                mmabf(acc[mt][nt], al[mt], bh);
            }
        }
    }
}

__global__ void __launch_bounds__(THREADS, 1)
hd_mma(const float* __restrict__ l0, const float* __restrict__ l1,
       const float* __restrict__ Wv1, const float* __restrict__ W1a,
       const float* __restrict__ b1a, const float* __restrict__ W1b,
       const float* __restrict__ b1b, const float* __restrict__ Wv2,
       const float* __restrict__ W2a, const float* __restrict__ b2a,
       const float* __restrict__ W2b, const float* __restrict__ b2b,
       float* __restrict__ out)
{
    extern __shared__ char smc[];
    float* SMF = reinterpret_cast<float*>(smc + B_SMALL);
    float* GATEF = reinterpret_cast<float*>(smc + B_GATE);
    float* DARR = reinterpret_cast<float*>(smc + B_DARR);
    float* PM0 = reinterpret_cast<float*>(smc + B_PM0);
    float* PM1 = reinterpret_cast<float*>(smc + B_PM1);
    const u32 sbase = s2u(smc);
    const u32 actH = sbase + B_ACTH;
    const int t = threadIdx.x, w = t >> 5, lane = t & 31;
    const int wm = w >> 1, wn = w & 1;
    const int m0 = 32 * wm;
    const int g = lane >> 2, tig = lane & 3;
    const int rA = (lane & 7) + ((lane >> 3) & 1) * 8;
    const int kh = (lane >> 4) & 1;

    /* ---- one-time weight staging ---- */
    for (int i = t; i < 16384; i += THREADS) wst(smc, B_WV1H, B_WV1L, 256, i >> 7, i & 127, Wv1[i]);
    for (int i = t; i < 12288; i += THREADS) wst(smc, B_W1AH, B_W1AL, 128, i >> 6, i & 63, W1a[i]);
    for (int i = t; i < 8192;  i += THREADS) wst(smc, B_W1BH, B_W1BL, 256, i >> 7, i & 127, W1b[i]);
    if (t < 64)  SMF[SB_B1A + t] = b1a[t];
    if (t < 128) SMF[SB_B1B + t] = b1b[t];
    if (t < 128) SMF[SB_WV2 + t] = Wv2[t];
    if (t < 65)  SMF[SB_W2A + t] = W2a[t];
    if (t == 0) { SMF[SB_C] = b2a[0]; SMF[SB_C + 1] = W2b[1]; SMF[SB_C + 2] = b2b[1]; }

    for (int blk = blockIdx.x; blk < NBLK; blk += GRID) {
        const float* l1b = l1 + (size_t)blk * 49152;
        const float* l0b = l0 + (size_t)blk * 16384;

        __syncthreads();  /* prior final reads done (and weights on iter 0) */
        for (int i = t; i < 768; i += THREADS) PM0[i] = 0.f;  /* PM0+PM1 contiguous */

        /* ===== G1a: vV half (cols 0..63) of vmix per chunk; norms in regs ===== */
        float vn2[2][4][4];
        #pragma unroll
        for (int a = 0; a < 2; a++)
            #pragma unroll
            for (int b = 0; b < 4; b++)
                #pragma unroll
                for (int c = 0; c < 4; c++) vn2[a][b][c] = 0.f;

        #pragma unroll 1
        for (int c = 0; c < 3; c++) {
            float acc[2][4][4];
            #pragma unroll
            for (int a = 0; a < 2; a++)
                #pragma unroll
                for (int b = 0; b < 4; b++)
                    #pragma unroll
                    for (int j = 0; j < 4; j++) acc[a][b][j] = 0.f;
            #pragma unroll 1
            for (int p = 0; p < 2; p++) {
                __syncthreads();
                #pragma unroll
                for (int jj = 0; jj < 8; jj++) {
                    int flat = jj * THREADS + t;
                    int row = flat >> 4, k4 = (flat & 15) << 2;
                    float4 v = *reinterpret_cast<const float4*>(l1b + (size_t)row * 384 + c * 128 + p * 64 + k4);
                    act_st4(smc, row, k4, v);
                }
                __syncthreads();
                gemm_passg<2, 4, 4>(acc, actH, m0, rA, kh,
                                    sbase + B_WV1H, 32768u, 256, 32 * wn, p * 64, lane);
            }
            #pragma unroll
            for (int a = 0; a < 2; a++)
                #pragma unroll
                for (int b = 0; b < 4; b++)
                    #pragma unroll
                    for (int j = 0; j < 4; j++) vn2[a][b][j] += acc[a][b][j] * acc[a][b][j];
        }

        /* ===== G2: h = silu(ctx @ W1a + b1a), ctx = [l0 | vn] ===== */
        float acc2[2][4][4];
        #pragma unroll
        for (int a = 0; a < 2; a++)
            #pragma unroll
            for (int b = 0; b < 4; b++)
                #pragma unroll
                for (int j = 0; j < 4; j++) acc2[a][b][j] = 0.f;
        #pragma unroll 1
        for (int p = 0; p < 3; p++) {
            __syncthreads();
            if (p < 2) {
                #pragma unroll
                for (int jj = 0; jj < 8; jj++) {
                    int flat = jj * THREADS + t;
                    int row = flat >> 4, k4 = (flat & 15) << 2;
                    float4 v = *reinterpret_cast<const float4*>(l0b + (size_t)row * 128 + p * 64 + k4);
                    act_st4(smc, row, k4, v);
                }
            } else {
                #pragma unroll
                for (int mt = 0; mt < 2; mt++)
                    #pragma unroll
                    for (int nt = 0; nt < 4; nt++)
                        #pragma unroll
                        for (int j = 0; j < 4; j++) {
                            int row = m0 + 16 * mt + g + (j >> 1) * 8;
                            int f = 32 * wn + 8 * nt + 2 * tig + (j & 1);
                            act_st1(smc, row, f, sqrtf(vn2[mt][nt][j]));
                        }
            }
            __syncthreads();
            gemm_passg<2, 4, 4>(acc2, actH, m0, rA, kh,
                                sbase + B_W1AH, 24576u, 128, 32 * wn, p * 64, lane);
        }

        /* ===== stage h = silu(acc2 + b1a) ===== */
        __syncthreads();
        #pragma unroll
        for (int mt = 0; mt < 2; mt++)
            #pragma unroll
            for (int nt = 0; nt < 4; nt++)
                #pragma unroll
                for (int j = 0; j < 4; j++) {
                    int row = m0 + 16 * mt + g + (j >> 1) * 8;
                    int f = 32 * wn + 8 * nt + 2 * tig + (j & 1);
                    act_st1(smc, row, f, silu(acc2[mt][nt][j] + SMF[SB_B1A + f]));
                }
        __syncthreads();

        /* ===== G3: y = h @ W1b + b1b ===== */
        float acc3[2][8][4];
        #pragma unroll
        for (int a = 0; a < 2; a++)
            #pragma unroll
            for (int b = 0; b < 8; b++)
                #pragma unroll
                for (int j = 0; j < 4; j++) acc3[a][b][j] = 0.f;
        gemm_passg<2, 8, 4>(acc3, actH, m0, rA, kh,
                            sbase + B_W1BH, 16384u, 256, 64 * wn, 0, lane);

        if (wn == 0) {  /* s_out -> per-atom dot with W2a */
            float rp[2][2] = {{0.f, 0.f}, {0.f, 0.f}};
            #pragma unroll
            for (int mt = 0; mt < 2; mt++)
                #pragma unroll
                for (int nt = 0; nt < 8; nt++)
                    #pragma unroll
                    for (int j = 0; j < 4; j++) {
                        int f = 8 * nt + 2 * tig + (j & 1);
                        rp[mt][j >> 1] += silu(acc3[mt][nt][j] + SMF[SB_B1B + f]) * SMF[SB_W2A + f];
                    }
            #pragma unroll
            for (int mt = 0; mt < 2; mt++)
                #pragma unroll
                for (int h2 = 0; h2 < 2; h2++) {
                    rp[mt][h2] += __shfl_xor_sync(0xffffffffu, rp[mt][h2], 1);
                    rp[mt][h2] += __shfl_xor_sync(0xffffffffu, rp[mt][h2], 2);
                    if (tig == 0) DARR[m0 + 16 * mt + g + 8 * h2] = rp[mt][h2];
                }
        } else {        /* gate -> smem */
            #pragma unroll
            for (int mt = 0; mt < 2; mt++)
                #pragma unroll
                for (int nt = 0; nt < 8; nt++)
                    #pragma unroll
                    for (int j = 0; j < 4; j++) {
                        int row = m0 + 16 * mt + g + (j >> 1) * 8;
                        int f = 8 * nt + 2 * tig + (j & 1);
                        GATEF[row * GATE_P + f] = acc3[mt][nt][j] + SMF[SB_B1B + 64 + f];
                    }
        }

        /* ===== G1b: vW half (cols 64..127), consume immediately ===== */
        #pragma unroll 1
        for (int c = 0; c < 3; c++) {
            float accw[2][4][4];
            #pragma unroll
            for (int a = 0; a < 2; a++)
                #pragma unroll
                for (int b = 0; b < 4; b++)
                    #pragma unroll
                    for (int j = 0; j < 4; j++) accw[a][b][j] = 0.f;
            #pragma unroll 1
            for (int p = 0; p < 2; p++) {
                __syncthreads();
                #pragma unroll
                for (int jj = 0; jj < 8; jj++) {
                    int flat = jj * THREADS + t;
                    int row = flat >> 4, k4 = (flat & 15) << 2;
                    float4 v = *reinterpret_cast<const float4*>(l1b + (size_t)row * 384 + c * 128 + p * 64 + k4);
                    act_st4(smc, row, k4, v);
                }
                __syncthreads();
                gemm_passg<2, 4, 4>(accw, actH, m0, rA, kh,
                                    sbase + B_WV1H, 32768u, 256, 64 + 32 * wn, p * 64, lane);
            }
            float q0[2][2] = {{0.f, 0.f}, {0.f, 0.f}}, q1[2][2] = {{0.f, 0.f}, {0.f, 0.f}};
            #pragma unroll
            for (int mt = 0; mt < 2; mt++)
                #pragma unroll
                for (int nt = 0; nt < 4; nt++)
                    #pragma unroll
                    for (int j = 0; j < 4; j++) {
                        int row = m0 + 16 * mt + g + (j >> 1) * 8;
                        int f = 32 * wn + 8 * nt + 2 * tig + (j & 1);
                        float pr = GATEF[row * GATE_P + f] * accw[mt][nt][j];
                        q0[mt][j >> 1] += pr * SMF[SB_WV2 + 2 * f];
                        q1[mt][j >> 1] += pr * SMF[SB_WV2 + 2 * f + 1];
                    }
            #pragma unroll
            for (int mt = 0; mt < 2; mt++)
                #pragma unroll
                for (int h2 = 0; h2 < 2; h2++) {
                    q0[mt][h2] += __shfl_xor_sync(0xffffffffu, q0[mt][h2], 1);
                    q0[mt][h2] += __shfl_xor_sync(0xffffffffu, q0[mt][h2], 2);
                    q1[mt][h2] += __shfl_xor_sync(0xffffffffu, q1[mt][h2], 1);
                    q1[mt][h2] += __shfl_xor_sync(0xffffffffu, q1[mt][h2], 2);
                    if (tig == 0) {
                        int row = m0 + 16 * mt + g + 8 * h2;
                        atomicAdd(&PM0[row * 3 + c], q0[mt][h2]);
                        atomicAdd(&PM1[row * 3 + c], q1[mt][h2]);
                    }
                }
        }

        /* ===== final per-atom scalar head + output ===== */
        __syncthreads();
        if (t < 128) {
            float a0 = PM0[t * 3], a1 = PM0[t * 3 + 1], a2 = PM0[t * 3 + 2];
            float q = sqrtf(a0 * a0 + a1 * a1 + a2 * a2);
            float dt = DARR[t] + SMF[SB_C] + q * SMF[SB_W2A + 64];
            float g2 = 1000.f * (silu(dt) * SMF[SB_C + 1] + SMF[SB_C + 2]);
            size_t ob = ((size_t)blk * 128 + t) * 3;
            out[ob + 0] = g2 * PM1[t * 3];
            out[ob + 1] = g2 * PM1[t * 3 + 1];
            out[ob + 2] = g2 * PM1[t * 3 + 2];
        }
    }
}

extern "C" void kernel_launch(void* const* d_in, const int* in_sizes, int n_in,
                              void* d_out, int out_size) {
    const float* l0  = (const float*)d_in[0];
    const float* l1  = (const float*)d_in[1];
    /* d_in[2] = idx_m (unused) */
    const float* Wv1 = (const float*)d_in[3];
    const float* W1a = (const float*)d_in[4];
    const float* b1a = (const float*)d_in[5];
    const float* W1b = (const float*)d_in[6];
    const float* b1b = (const float*)d_in[7];
    const float* Wv2 = (const float*)d_in[8];
    const float* W2a = (const float*)d_in[9];
    const float* b2a = (const float*)d_in[10];
    const float* W2b = (const float*)d_in[11];
    const float* b2b = (const float*)d_in[12];

    cudaFuncSetAttribute(hd_mma, cudaFuncAttributeMaxDynamicSharedMemorySize, SMEM_BYTES);
    hd_mma<<<GRID, THREADS, SMEM_BYTES>>>(
        l0, l1, Wv1, W1a, b1a, W1b, b1b, Wv2, W2a, b2a, W2b, b2b, (float*)d_out);
}

// round 6
// speedup vs baseline: 2.8110x; 1.2074x over previous
#include <cuda_runtime.h>
#include <cuda_bf16.h>
#include <cstdint>

typedef uint32_t u32;

#define THREADS 512
#define GRID    148
#define NBLK    2048

/* ---- smem byte offsets ---- */
#define B_WV1H 0        /* Wv1 [128k][128n] bf16 hi, XOR-swizzled, 32768 */
#define B_WV1L 32768
#define B_W1AH 65536    /* W1a [192k][64n] 24576 */
#define B_W1AL 90112
#define B_W1BH 114688   /* W1b [64k][128n] 16384 */
#define B_W1BL 131072
#define B_ACTH 147456   /* act [128m][64k] bf16 16384 */
#define B_ACTL 163840
#define B_GATE 180224   /* f32 [128][68] = 34816 */
#define GATE_P 68
#define B_DARR 215040   /* f32 [128] */
#define B_PM0  215552   /* f32 [128][3] */
#define B_PM1  217088   /* f32 [128][3] */
#define B_SMALL 218624  /* biases etc */
#define SMEM_BYTES 220288

#define SB_B1A 0
#define SB_B1B 64
#define SB_WV2 192
#define SB_W2A 320
#define SB_C   385   /* b2a, W2b[1], b2b[1] */

static __device__ __forceinline__ u32 s2u(const void* p) {
    u32 a; asm("{ .reg .u64 t; cvta.to.shared.u64 t, %1; cvt.u32.u64 %0, t; }" : "=r"(a) : "l"(p)); return a;
}
static __device__ __forceinline__ void ldmx4(u32& r0, u32& r1, u32& r2, u32& r3, u32 a) {
    asm volatile("ldmatrix.sync.aligned.m8n8.x4.shared.b16 {%0,%1,%2,%3}, [%4];"
                 : "=r"(r0), "=r"(r1), "=r"(r2), "=r"(r3) : "r"(a));
}
static __device__ __forceinline__ void ldmx2t(u32& r0, u32& r1, u32 a) {
    asm volatile("ldmatrix.sync.aligned.m8n8.x2.trans.shared.b16 {%0,%1}, [%2];"
                 : "=r"(r0), "=r"(r1) : "r"(a));
}
static __device__ __forceinline__ void mmabf(float* d, const u32* a, const u32* b) {
    asm volatile("mma.sync.aligned.m16n8k16.row.col.f32.bf16.bf16.f32 "
                 "{%0,%1,%2,%3}, {%4,%5,%6,%7}, {%8,%9}, {%0,%1,%2,%3};"
                 : "+f"(d[0]), "+f"(d[1]), "+f"(d[2]), "+f"(d[3])
                 : "r"(a[0]), "r"(a[1]), "r"(a[2]), "r"(a[3]), "r"(b[0]), "r"(b[1]));
}
static __device__ __forceinline__ float silu(float x) {
    return x * (1.0f / (1.0f + __expf(-x)));
}
static __device__ __forceinline__ void split2(float x, float y, u32& hi, u32& lo) {
    __nv_bfloat16 hx = __float2bfloat16(x), hy = __float2bfloat16(y);
    __nv_bfloat16 lx = __float2bfloat16(x - __bfloat162float(hx));
    __nv_bfloat16 ly = __float2bfloat16(y - __bfloat162float(hy));
    hi = (u32)__bfloat16_as_ushort(hx) | ((u32)__bfloat16_as_ushort(hy) << 16);
    lo = (u32)__bfloat16_as_ushort(lx) | ((u32)__bfloat16_as_ushort(ly) << 16);
}
static __device__ __forceinline__ void wst(char* smc, int offH, int offL, int rowB,
                                           int k, int n, float x) {
    __nv_bfloat16 h = __float2bfloat16(x);
    __nv_bfloat16 l = __float2bfloat16(x - __bfloat162float(h));
    int off = k * rowB + ((((n >> 3) ^ (k & 7))) << 4) + ((n & 7) << 1);
    *reinterpret_cast<__nv_bfloat16*>(smc + offH + off) = h;
    *reinterpret_cast<__nv_bfloat16*>(smc + offL + off) = l;
}
static __device__ __forceinline__ void act_st4(char* smc, int row, int k4, float4 v) {
    u32 h0, l0, h1, l1;
    split2(v.x, v.y, h0, l0); split2(v.z, v.w, h1, l1);
    int off = row * 128 + ((((k4 >> 3) ^ (row & 7))) << 4) + ((k4 & 7) << 1);
    *reinterpret_cast<uint2*>(smc + B_ACTH + off) = make_uint2(h0, h1);
    *reinterpret_cast<uint2*>(smc + B_ACTL + off) = make_uint2(l0, l1);
}
static __device__ __forceinline__ void act_st1(char* smc, int row, int k, float x) {
    __nv_bfloat16 h = __float2bfloat16(x);
    __nv_bfloat16 l = __float2bfloat16(x - __bfloat162float(h));
    int off = row * 128 + ((((k >> 3) ^ (row & 7))) << 4) + ((k & 7) << 1);
    *reinterpret_cast<__nv_bfloat16*>(smc + B_ACTH + off) = h;
    *reinterpret_cast<__nv_bfloat16*>(smc + B_ACTL + off) = l;
}

/* one GEMM pass over the staged 64-k activation buffer; MT=1 (16 rows per warp) */
template<int NT, int KS>
static __device__ __forceinline__ void gemm_passg(
    float (&acc)[NT][4], u32 actH, int m0, int rA, int kh,
    u32 bH, u32 gap, int rowB, int n0, int kg0, int lane)
{
    #pragma unroll
    for (int s = 0; s < KS; s++) {
        u32 ah[4], al[4];
        {
            int row = m0 + rA;
            u32 a = actH + row * 128 + ((((2 * s + kh) ^ (row & 7))) << 4);
            ldmx4(ah[0], ah[1], ah[2], ah[3], a);
            ldmx4(al[0], al[1], al[2], al[3], a + 16384u);
        }
        int kb = kg0 + s * 16 + (lane & 15);
        #pragma unroll
        for (int nt = 0; nt < NT; nt++) {
            int n = n0 + nt * 8;
            u32 b = bH + kb * rowB + ((((n >> 3) ^ (kb & 7))) << 4);
            u32 bh[2], bl[2];
            ldmx2t(bh[0], bh[1], b);
            ldmx2t(bl[0], bl[1], b + gap);
            mmabf(acc[nt], ah, bh);
            mmabf(acc[nt], ah, bl);
            mmabf(acc[nt], al, bh);
        }
    }
}

__global__ void __launch_bounds__(THREADS, 1)
hd_mma(const float* __restrict__ l0, const float* __restrict__ l1,
       const float* __restrict__ Wv1, const float* __restrict__ W1a,
       const float* __restrict__ b1a, const float* __restrict__ W1b,
       const float* __restrict__ b1b, const float* __restrict__ Wv2,
       const float* __restrict__ W2a, const float* __restrict__ b2a,
       const float* __restrict__ W2b, const float* __restrict__ b2b,
       float* __restrict__ out)
{
    extern __shared__ char smc[];
    float* SMF = reinterpret_cast<float*>(smc + B_SMALL);
    float* GATEF = reinterpret_cast<float*>(smc + B_GATE);
    float* DARR = reinterpret_cast<float*>(smc + B_DARR);
    float* PM0 = reinterpret_cast<float*>(smc + B_PM0);
    float* PM1 = reinterpret_cast<float*>(smc + B_PM1);
    const u32 sbase = s2u(smc);
    const u32 actH = sbase + B_ACTH;
    const int t = threadIdx.x, w = t >> 5, lane = t & 31;
    const int wm = w >> 1, wn = w & 1;
    const int m0 = 16 * wm;                 /* 8 m-slices of 16 rows */
    const int g = lane >> 2, tig = lane & 3;
    const int rA = (lane & 7) + ((lane >> 3) & 1) * 8;
    const int kh = (lane >> 4) & 1;

    /* ---- one-time weight staging ---- */
    for (int i = t; i < 16384; i += THREADS) wst(smc, B_WV1H, B_WV1L, 256, i >> 7, i & 127, Wv1[i]);
    for (int i = t; i < 12288; i += THREADS) wst(smc, B_W1AH, B_W1AL, 128, i >> 6, i & 63, W1a[i]);
    for (int i = t; i < 8192;  i += THREADS) wst(smc, B_W1BH, B_W1BL, 256, i >> 7, i & 127, W1b[i]);
    if (t < 64)  SMF[SB_B1A + t] = b1a[t];
    if (t < 128) SMF[SB_B1B + t] = b1b[t];
    if (t < 128) SMF[SB_WV2 + t] = Wv2[t];
    if (t < 65)  SMF[SB_W2A + t] = W2a[t];
    if (t == 0) { SMF[SB_C] = b2a[0]; SMF[SB_C + 1] = W2b[1]; SMF[SB_C + 2] = b2b[1]; }

    for (int blk = blockIdx.x; blk < NBLK; blk += GRID) {
        const float* l1b = l1 + (size_t)blk * 49152;
        const float* l0b = l0 + (size_t)blk * 16384;

        __syncthreads();
        for (int i = t; i < 768; i += THREADS) PM0[i] = 0.f;  /* PM0+PM1 contiguous */

        /* ===== G1a: vV half (cols 0..63); norms accumulated in regs ===== */
        float vn2[4][4];
        #pragma unroll
        for (int b = 0; b < 4; b++)
            #pragma unroll
            for (int c = 0; c < 4; c++) vn2[b][c] = 0.f;

        #pragma unroll 1
        for (int c = 0; c < 3; c++) {
            float acc[4][4];
            #pragma unroll
            for (int b = 0; b < 4; b++)
                #pragma unroll
                for (int j = 0; j < 4; j++) acc[b][j] = 0.f;
            #pragma unroll 1
            for (int p = 0; p < 2; p++) {
                __syncthreads();
                #pragma unroll
                for (int jj = 0; jj < 4; jj++) {
                    int flat = jj * THREADS + t;
                    int row = flat >> 4, k4 = (flat & 15) << 2;
                    float4 v = *reinterpret_cast<const float4*>(l1b + (size_t)row * 384 + c * 128 + p * 64 + k4);
                    act_st4(smc, row, k4, v);
                }
                __syncthreads();
                gemm_passg<4, 4>(acc, actH, m0, rA, kh,
                                 sbase + B_WV1H, 32768u, 256, 32 * wn, p * 64, lane);
            }
            #pragma unroll
            for (int b = 0; b < 4; b++)
                #pragma unroll
                for (int j = 0; j < 4; j++) vn2[b][j] += acc[b][j] * acc[b][j];
        }

        /* ===== G2: h = silu(ctx @ W1a + b1a), ctx = [l0 | vn] ===== */
        float acc2[4][4];
        #pragma unroll
        for (int b = 0; b < 4; b++)
            #pragma unroll
            for (int j = 0; j < 4; j++) acc2[b][j] = 0.f;
        #pragma unroll 1
        for (int p = 0; p < 3; p++) {
            __syncthreads();
            if (p < 2) {
                #pragma unroll
                for (int jj = 0; jj < 4; jj++) {
                    int flat = jj * THREADS + t;
                    int row = flat >> 4, k4 = (flat & 15) << 2;
                    float4 v = *reinterpret_cast<const float4*>(l0b + (size_t)row * 128 + p * 64 + k4);
                    act_st4(smc, row, k4, v);
                }
            } else {
                #pragma unroll
                for (int nt = 0; nt < 4; nt++)
                    #pragma unroll
                    for (int j = 0; j < 4; j++) {
                        int row = m0 + g + (j >> 1) * 8;
                        int f = 32 * wn + 8 * nt + 2 * tig + (j & 1);
                        act_st1(smc, row, f, sqrtf(vn2[nt][j]));
                    }
            }
            __syncthreads();
            gemm_passg<4, 4>(acc2, actH, m0, rA, kh,
                             sbase + B_W1AH, 24576u, 128, 32 * wn, p * 64, lane);
        }

        /* ===== stage h = silu(acc2 + b1a) ===== */
        __syncthreads();
        #pragma unroll
        for (int nt = 0; nt < 4; nt++)
            #pragma unroll
            for (int j = 0; j < 4; j++) {
                int row = m0 + g + (j >> 1) * 8;
                int f = 32 * wn + 8 * nt + 2 * tig + (j & 1);
                act_st1(smc, row, f, silu(acc2[nt][j] + SMF[SB_B1A + f]));
            }
        __syncthreads();

        /* ===== G3: y = h @ W1b + b1b ===== */
        float acc3[8][4];
        #pragma unroll
        for (int b = 0; b < 8; b++)
            #pragma unroll
            for (int j = 0; j < 4; j++) acc3[b][j] = 0.f;
        gemm_passg<8, 4>(acc3, actH, m0, rA, kh,
                         sbase + B_W1BH, 16384u, 256, 64 * wn, 0, lane);

        if (wn == 0) {  /* s_out -> per-atom dot with W2a */
            float rp[2] = {0.f, 0.f};
            #pragma unroll
            for (int nt = 0; nt < 8; nt++)
                #pragma unroll
                for (int j = 0; j < 4; j++) {
                    int f = 8 * nt + 2 * tig + (j & 1);
                    rp[j >> 1] += silu(acc3[nt][j] + SMF[SB_B1B + f]) * SMF[SB_W2A + f];
                }
            #pragma unroll
            for (int h2 = 0; h2 < 2; h2++) {
                rp[h2] += __shfl_xor_sync(0xffffffffu, rp[h2], 1);
                rp[h2] += __shfl_xor_sync(0xffffffffu, rp[h2], 2);
                if (tig == 0) DARR[m0 + g + 8 * h2] = rp[h2];
            }
        } else {        /* gate -> smem */
            #pragma unroll
            for (int nt = 0; nt < 8; nt++)
                #pragma unroll
                for (int j = 0; j < 4; j++) {
                    int row = m0 + g + (j >> 1) * 8;
                    int f = 8 * nt + 2 * tig + (j & 1);
                    GATEF[row * GATE_P + f] = acc3[nt][j] + SMF[SB_B1B + 64 + f];
                }
        }

        /* ===== G1b: vW half (cols 64..127), consume immediately ===== */
        #pragma unroll 1
        for (int c = 0; c < 3; c++) {
            float accw[4][4];
            #pragma unroll
            for (int b = 0; b < 4; b++)
                #pragma unroll
                for (int j = 0; j < 4; j++) accw[b][j] = 0.f;
            #pragma unroll 1
            for (int p = 0; p < 2; p++) {
                __syncthreads();
                #pragma unroll
                for (int jj = 0; jj < 4; jj++) {
                    int flat = jj * THREADS + t;
                    int row = flat >> 4, k4 = (flat & 15) << 2;
                    float4 v = *reinterpret_cast<const float4*>(l1b + (size_t)row * 384 + c * 128 + p * 64 + k4);
                    act_st4(smc, row, k4, v);
                }
                __syncthreads();
                gemm_passg<4, 4>(accw, actH, m0, rA, kh,
                                 sbase + B_WV1H, 32768u, 256, 64 + 32 * wn, p * 64, lane);
            }
            float q0[2] = {0.f, 0.f}, q1[2] = {0.f, 0.f};
            #pragma unroll
            for (int nt = 0; nt < 4; nt++)
                #pragma unroll
                for (int j = 0; j < 4; j++) {
                    int row = m0 + g + (j >> 1) * 8;
                    int f = 32 * wn + 8 * nt + 2 * tig + (j & 1);
                    float pr = GATEF[row * GATE_P + f] * accw[nt][j];
                    q0[j >> 1] += pr * SMF[SB_WV2 + 2 * f];
                    q1[j >> 1] += pr * SMF[SB_WV2 + 2 * f + 1];
                }
            #pragma unroll
            for (int h2 = 0; h2 < 2; h2++) {
                q0[h2] += __shfl_xor_sync(0xffffffffu, q0[h2], 1);
                q0[h2] += __shfl_xor_sync(0xffffffffu, q0[h2], 2);
                q1[h2] += __shfl_xor_sync(0xffffffffu, q1[h2], 1);
                q1[h2] += __shfl_xor_sync(0xffffffffu, q1[h2], 2);
                if (tig == 0) {
                    int row = m0 + g + 8 * h2;
                    atomicAdd(&PM0[row * 3 + c], q0[h2]);
                    atomicAdd(&PM1[row * 3 + c], q1[h2]);
                }
            }
        }

        /* ===== final per-atom scalar head + output ===== */
        __syncthreads();
        if (t < 128) {
            float a0 = PM0[t * 3], a1 = PM0[t * 3 + 1], a2 = PM0[t * 3 + 2];
            float q = sqrtf(a0 * a0 + a1 * a1 + a2 * a2);
            float dt = DARR[t] + SMF[SB_C] + q * SMF[SB_W2A + 64];
            float g2 = 1000.f * (silu(dt) * SMF[SB_C + 1] + SMF[SB_C + 2]);
            size_t ob = ((size_t)blk * 128 + t) * 3;
            out[ob + 0] = g2 * PM1[t * 3];
            out[ob + 1] = g2 * PM1[t * 3 + 1];
            out[ob + 2] = g2 * PM1[t * 3 + 2];
        }
    }
}

extern "C" void kernel_launch(void* const* d_in, const int* in_sizes, int n_in,
                              void* d_out, int out_size) {
    const float* l0  = (const float*)d_in[0];
    const float* l1  = (const float*)d_in[1];
    /* d_in[2] = idx_m (unused) */
    const float* Wv1 = (const float*)d_in[3];
    const float* W1a = (const float*)d_in[4];
    const float* b1a = (const float*)d_in[5];
    const float* W1b = (const float*)d_in[6];
    const float* b1b = (const float*)d_in[7];
    const float* Wv2 = (const float*)d_in[8];
    const float* W2a = (const float*)d_in[9];
    const float* b2a = (const float*)d_in[10];
    const float* W2b = (const float*)d_in[11];
    const float* b2b = (const float*)d_in[12];

    cudaFuncSetAttribute(hd_mma, cudaFuncAttributeMaxDynamicSharedMemorySize, SMEM_BYTES);
    hd_mma<<<GRID, THREADS, SMEM_BYTES>>>(
        l0, l1, Wv1, W1a, b1a, W1b, b1b, Wv2, W2a, b2a, W2b, b2b, (float*)d_out);
}